// round 10
// baseline (speedup 1.0000x reference)
#include <cuda_runtime.h>
#include <cstdint>

// BroadcastTC on GB300, round 10: symmetric 3-way role split.
// npairs = B*C = 1,048,576; t1,t2 = 27 fp32 per pair.
//   out1[xy,uv] = sum_k t1[xy*3+k]*t2[k*9+uv] / sqrt(3)   (81 floats)
//   out2[x,u]   = sum_kl t1[x*9+kl]*t2[kl*3+u] / 3        (9 floats)
//   out3        = dot(t1,t2) / sqrt(27)                   (1 float)
// Output layout: [out1 flat | out2 flat | out3 flat].
//
// Role r = tid>>6 (warp-uniform, 0..2); pair p = tid&63. Role r owns
// a[j] = t1[9r+j] (9 floats) + all of b = t2 (27 floats) and computes:
//   out1 rows xy = 3r..3r+2   (t1[xy*3+k] = a[3i+k], i = xy-3r)
//   out2 row  x  = r          (fully -- no cross-role combine)
//   out3 partial sum_{j} a[j]*b[9r+j]   (role 0 combines)
// Straight-line code, no divergent role branches, 36 live input regs.

#define PPB 64
#define THREADS 192

__device__ __forceinline__ uint32_t smem_u32(const void* p) {
    uint32_t a;
    asm("{ .reg .u64 t; cvta.to.shared.u64 t, %1; cvt.u32.u64 %0, t; }"
        : "=r"(a) : "l"(p));
    return a;
}

__global__ __launch_bounds__(THREADS, 6)
void broadcast_tc_kernel(const float* __restrict__ T1,
                         const float* __restrict__ T2,
                         float* __restrict__ out,
                         int npairs)
{
    // s: inputs (t1 at [0..1727], t2 at [1728..3455]) then out1 staging.
    __shared__ __align__(16) float s[PPB * 81];    // 20736 B
    __shared__ __align__(16) float st2[PPB * 9];   // 2304 B (out2 staging)
    __shared__ float aux[PPB * 2];                 // 512 B (out3 partials r=1,2)

    const int tid  = threadIdx.x;
    const int p    = tid & (PPB - 1);
    const int role = tid >> 6;                     // warp-uniform, 0..2
    const long long p0 = (long long)blockIdx.x * PPB;

    // ---- Phase 1: cp.async input staging (864 float4, L1-bypass) ----
    {
        const float4* g1 = (const float4*)(T1 + p0 * 27);   // 432 float4
        const float4* g2 = (const float4*)(T2 + p0 * 27);   // 432 float4
        const uint32_t sb = smem_u32(s);
        #pragma unroll
        for (int t = 0; t < 5; t++) {
            const int i = tid + t * THREADS;
            if (i < 864) {
                const float4* src = (i < 432) ? (g1 + i) : (g2 + (i - 432));
                asm volatile("cp.async.cg.shared.global [%0], [%1], 16;"
                             :: "r"(sb + i * 16), "l"(src) : "memory");
            }
        }
        asm volatile("cp.async.commit_group;" ::: "memory");
        asm volatile("cp.async.wait_group 0;" ::: "memory");
    }
    __syncthreads();   // B1: inputs visible

    // ---- Phase 2: per-role register gather (strides 27: conflict-free) ----
    float b[27], a[9];   // a[j] = t1[9*role + j]
    #pragma unroll
    for (int j = 0; j < 27; j++) b[j] = s[PPB * 27 + p * 27 + j];
    {
        const int ab = p * 27 + role * 9;
        #pragma unroll
        for (int j = 0; j < 9; j++) a[j] = s[ab + j];
    }
    __syncthreads();   // B2: inputs consumed; s reusable for out1 staging

    const float n1 = 0.5773502691896258f;   // 1/sqrt(3)
    const float n2 = 0.3333333333333333f;   // 1/3
    const float n3 = 0.1924500897298753f;   // 1/sqrt(27)

    // ---- out1 rows xy = 3*role + i, i = 0..2 -> s ----
    {
        const int base = p * 81 + role * 27;
        #pragma unroll
        for (int i = 0; i < 3; i++) {
            const float c0 = a[i * 3 + 0] * n1;
            const float c1 = a[i * 3 + 1] * n1;
            const float c2 = a[i * 3 + 2] * n1;
            #pragma unroll
            for (int uv = 0; uv < 9; uv++)
                s[base + i * 9 + uv] = c0 * b[uv] + c1 * b[9 + uv] + c2 * b[18 + uv];
        }
    }

    // ---- out2 row x = role (full) -> st2 ----
    #pragma unroll
    for (int u = 0; u < 3; u++) {
        float r = 0.0f;
        #pragma unroll
        for (int kl = 0; kl < 9; kl++) r += a[kl] * b[kl * 3 + u];
        st2[p * 9 + role * 3 + u] = r * n2;
    }

    // ---- out3 partial: sum_j a[j] * b[9*role + j] ----
    float d = 0.0f;
    #pragma unroll
    for (int j = 0; j < 9; j++) d += a[j] * b[role * 9 + j];
    if (role != 0) aux[p * 2 + (role - 1)] = d;

    __syncthreads();   // B3: out1/out2 staged; out3 partials published

    if (role == 0) {
        // out3: combine + coalesced streaming store (64 contiguous floats)
        __stcs(out + (long long)npairs * 90 + p0 + p,
               (d + aux[p * 2 + 0] + aux[p * 2 + 1]) * n3);
    }

    // ---- Copy out1: 1296 float4, fully coalesced ----
    {
        float4* o1 = (float4*)(out + p0 * 81);
        const float4* sv = (const float4*)s;
        #pragma unroll
        for (int t = 0; t < 7; t++) {
            const int i = tid + t * THREADS;
            if (i < PPB * 81 / 4) __stcs(o1 + i, sv[i]);
        }
    }

    // ---- Copy out2: 144 float4 ----
    {
        float4* o2 = (float4*)(out + (long long)npairs * 81 + p0 * 9);
        const float4* sv = (const float4*)st2;
        if (tid < PPB * 9 / 4) __stcs(o2 + tid, sv[tid]);
    }
}

extern "C" void kernel_launch(void* const* d_in, const int* in_sizes, int n_in,
                              void* d_out, int out_size)
{
    const float* T1 = (const float*)d_in[0];
    const float* T2 = (const float*)d_in[1];
    float* out = (float*)d_out;

    const int npairs = in_sizes[0] / 27;     // 1,048,576
    const int grid = npairs / PPB;           // 16384

    broadcast_tc_kernel<<<grid, THREADS>>>(T1, T2, out, npairs);
}

// round 11
// speedup vs baseline: 1.1266x; 1.1266x over previous
#include <cuda_runtime.h>
#include <cstdint>

// BroadcastTC on GB300, round 11: R9 pipeline x 2 tiles per block, with
// zero-cost L2 prefetch of tile 1 issued before tile 0 is processed.
// npairs = B*C = 1,048,576; t1,t2 = 27 fp32 per pair.
//   out1[xy,uv] = sum_k t1[xy*3+k]*t2[k*9+uv] / sqrt(3)   (81 floats)
//   out2[x,u]   = sum_kl t1[x*9+kl]*t2[kl*3+u] / 3        (9 floats)
//   out3        = dot(t1,t2) / sqrt(27)                   (1 float)
// Output layout: [out1 flat | out2 flat | out3 flat].
//
// Role split (warp-uniform): threads p (role 0) and p+64 (role 1) share pair p.

#define PPB 64
#define THREADS 128
#define TILES 2

__device__ __forceinline__ uint32_t smem_u32(const void* p) {
    uint32_t a;
    asm("{ .reg .u64 t; cvta.to.shared.u64 t, %1; cvt.u32.u64 %0, t; }"
        : "=r"(a) : "l"(p));
    return a;
}

__global__ __launch_bounds__(THREADS, 8)
void broadcast_tc_kernel(const float* __restrict__ T1,
                         const float* __restrict__ T2,
                         float* __restrict__ out,
                         int npairs)
{
    __shared__ __align__(16) float s[PPB * 81];    // 20736 B: inputs then out1 stage
    __shared__ __align__(16) float st2[PPB * 9];   // 2304 B: out2 staging
    __shared__ float aux[PPB * 4];                 // 1024 B: role-0 partials

    const int tid  = threadIdx.x;
    const int p    = tid & (PPB - 1);
    const int role = tid >> 6;                     // warp-uniform
    const long long tp0 = (long long)blockIdx.x * (PPB * TILES);

    const float n1 = 0.5773502691896258f;   // 1/sqrt(3)
    const float n2 = 0.3333333333333333f;   // 1/3
    const float n3 = 0.1924500897298753f;   // 1/sqrt(27)

    // ---- L2 prefetch of tile 1 inputs (108 x 128B lines, zero reg cost) ----
    {
        const long long p1 = tp0 + PPB;
        if (tid < 54) {
            const char* q = (const char*)(T1 + p1 * 27) + tid * 128;
            asm volatile("prefetch.global.L2 [%0];" :: "l"(q));
        } else if (tid < 108) {
            const char* q = (const char*)(T2 + p1 * 27) + (tid - 54) * 128;
            asm volatile("prefetch.global.L2 [%0];" :: "l"(q));
        }
    }

    for (int it = 0; it < TILES; it++) {
        const long long p0 = tp0 + (long long)it * PPB;

        // ---- Phase 1: cp.async input staging (864 float4, L1-bypass) ----
        {
            const float4* g1 = (const float4*)(T1 + p0 * 27);   // 432 float4
            const float4* g2 = (const float4*)(T2 + p0 * 27);   // 432 float4
            const uint32_t sb = smem_u32(s);
            #pragma unroll
            for (int t = 0; t < 7; t++) {
                const int i = tid + t * THREADS;
                if (i < 864) {
                    const float4* src = (i < 432) ? (g1 + i) : (g2 + (i - 432));
                    asm volatile("cp.async.cg.shared.global [%0], [%1], 16;"
                                 :: "r"(sb + i * 16), "l"(src) : "memory");
                }
            }
            asm volatile("cp.async.commit_group;" ::: "memory");
            asm volatile("cp.async.wait_group 0;" ::: "memory");
        }
        __syncthreads();   // B1: inputs visible

        // ---- Phase 2: per-role register gather (stride 27: conflict-free) ----
        float b[27], a[15];   // a[j] = t1[role*12 + j]
        #pragma unroll
        for (int j = 0; j < 27; j++) b[j] = s[PPB * 27 + p * 27 + j];
        {
            const int abase = p * 27 + role * 12;
            #pragma unroll
            for (int j = 0; j < 15; j++) a[j] = s[abase + j];
        }
        __syncthreads();   // B2: inputs consumed; s reusable

        float d;   // out3 partial

        if (role == 0) {
            // out1 rows xy = 0..3 -> s
            #pragma unroll
            for (int xy = 0; xy < 4; xy++) {
                const float c0 = a[xy * 3 + 0] * n1;
                const float c1 = a[xy * 3 + 1] * n1;
                const float c2 = a[xy * 3 + 2] * n1;
                #pragma unroll
                for (int uv = 0; uv < 9; uv++)
                    s[p * 81 + xy * 9 + uv] =
                        c0 * b[uv] + c1 * b[9 + uv] + c2 * b[18 + uv];
            }
            // out2 x=0 full -> st2 slots 0..2
            #pragma unroll
            for (int u = 0; u < 3; u++) {
                float r = 0.0f;
                #pragma unroll
                for (int kl = 0; kl < 9; kl++) r += a[kl] * b[kl * 3 + u];
                st2[p * 9 + u] = r * n2;
            }
            // out2 x=1 partial, kl=0..2 (t1[9..11]) -> aux
            #pragma unroll
            for (int u = 0; u < 3; u++)
                aux[p * 4 + u] = a[9] * b[u] + a[10] * b[3 + u] + a[11] * b[6 + u];
            // out3 partial j=0..11 -> aux
            d = 0.0f;
            #pragma unroll
            for (int j = 0; j < 12; j++) d += a[j] * b[j];
            aux[p * 4 + 3] = d;
        } else {
            // a[j] = t1[12+j]
            // out1 rows xy = 4..8 -> s
            #pragma unroll
            for (int xy = 4; xy < 9; xy++) {
                const float c0 = a[xy * 3 - 12] * n1;
                const float c1 = a[xy * 3 - 11] * n1;
                const float c2 = a[xy * 3 - 10] * n1;
                #pragma unroll
                for (int uv = 0; uv < 9; uv++)
                    s[p * 81 + xy * 9 + uv] =
                        c0 * b[uv] + c1 * b[9 + uv] + c2 * b[18 + uv];
            }
            // out2 x=2 full: t1[18+kl] = a[6+kl] -> st2 slots 6..8
            #pragma unroll
            for (int u = 0; u < 3; u++) {
                float r = 0.0f;
                #pragma unroll
                for (int kl = 0; kl < 9; kl++) r += a[6 + kl] * b[kl * 3 + u];
                st2[p * 9 + 6 + u] = r * n2;
            }
            // out3 partial j=12..26
            d = 0.0f;
            #pragma unroll
            for (int j = 0; j < 15; j++) d += a[j] * b[12 + j];
        }
        __syncthreads();   // B3: out1 staged; role-0 partials published

        if (role == 1) {
            // out2 x=1 combine -> st2 slots 3..5
            #pragma unroll
            for (int u = 0; u < 3; u++) {
                float r = aux[p * 4 + u];
                #pragma unroll
                for (int kl = 3; kl < 9; kl++) r += a[kl - 3] * b[kl * 3 + u];
                st2[p * 9 + 3 + u] = r * n2;
            }
            // out3 combine + coalesced streaming store
            __stcs(out + (long long)npairs * 90 + p0 + p,
                   (d + aux[p * 4 + 3]) * n3);
        }

        // ---- Copy out1: 1296 float4, fully coalesced ----
        {
            float4* o1 = (float4*)(out + p0 * 81);
            const float4* sv = (const float4*)s;
            #pragma unroll
            for (int i = tid; i < PPB * 81 / 4; i += THREADS)
                __stcs(o1 + i, sv[i]);
        }
        __syncthreads();   // B4: s free for next tile; st2 fully written

        // ---- Copy out2: 144 float4 ----
        {
            float4* o2 = (float4*)(out + (long long)npairs * 81 + p0 * 9);
            const float4* sv = (const float4*)st2;
            #pragma unroll
            for (int i = tid; i < PPB * 9 / 4; i += THREADS)
                __stcs(o2 + i, sv[i]);
        }
        // st2 reads complete before next tile's B2 (program order + B1/B2),
        // so no extra barrier needed here.
    }
}

extern "C" void kernel_launch(void* const* d_in, const int* in_sizes, int n_in,
                              void* d_out, int out_size)
{
    const float* T1 = (const float*)d_in[0];
    const float* T2 = (const float*)d_in[1];
    float* out = (float*)d_out;

    const int npairs = in_sizes[0] / 27;             // 1,048,576
    const int grid = npairs / (PPB * TILES);         // 8192

    broadcast_tc_kernel<<<grid, THREADS>>>(T1, T2, out, npairs);
}

// round 12
// speedup vs baseline: 1.1535x; 1.0239x over previous
#include <cuda_runtime.h>
#include <cstdint>

// BroadcastTC on GB300, round 12: R9 pipeline with async bulk-copy write-out
// (cp.async.bulk shared->global replaces ~360 per-warp STG.128 per block).
// npairs = B*C = 1,048,576; t1,t2 = 27 fp32 per pair.
//   out1[xy,uv] = sum_k t1[xy*3+k]*t2[k*9+uv] / sqrt(3)   (81 floats)
//   out2[x,u]   = sum_kl t1[x*9+kl]*t2[kl*3+u] / 3        (9 floats)
//   out3        = dot(t1,t2) / sqrt(27)                   (1 float)
// Output layout: [out1 flat | out2 flat | out3 flat].
//
// Role split (warp-uniform): threads p (role 0) and p+64 (role 1) share pair p.

#define PPB 64
#define THREADS 128

__device__ __forceinline__ uint32_t smem_u32(const void* p) {
    uint32_t a;
    asm("{ .reg .u64 t; cvta.to.shared.u64 t, %1; cvt.u32.u64 %0, t; }"
        : "=r"(a) : "l"(p));
    return a;
}

__global__ __launch_bounds__(THREADS, 8)
void broadcast_tc_kernel(const float* __restrict__ T1,
                         const float* __restrict__ T2,
                         float* __restrict__ out,
                         int npairs)
{
    // s: inputs (t1 at [0..1727], t2 at [1728..3455]) then out1 staging.
    __shared__ __align__(16) float s[PPB * 81];    // 20736 B
    __shared__ __align__(16) float st2[PPB * 9];   // 2304 B (out2 staging)
    __shared__ float aux[PPB * 4];                 // 1024 B (role-0 partials)

    const int tid  = threadIdx.x;
    const int p    = tid & (PPB - 1);
    const int role = tid >> 6;                     // warp-uniform
    const long long p0 = (long long)blockIdx.x * PPB;

    // ---- Phase 1: cp.async input staging (864 float4, L1-bypass) ----
    {
        const float4* g1 = (const float4*)(T1 + p0 * 27);   // 432 float4
        const float4* g2 = (const float4*)(T2 + p0 * 27);   // 432 float4
        const uint32_t sb = smem_u32(s);
        #pragma unroll
        for (int t = 0; t < 7; t++) {
            const int i = tid + t * THREADS;
            if (i < 864) {
                const float4* src = (i < 432) ? (g1 + i) : (g2 + (i - 432));
                asm volatile("cp.async.cg.shared.global [%0], [%1], 16;"
                             :: "r"(sb + i * 16), "l"(src) : "memory");
            }
        }
        asm volatile("cp.async.commit_group;" ::: "memory");
        asm volatile("cp.async.wait_group 0;" ::: "memory");
    }
    __syncthreads();   // B1: inputs visible

    // ---- Phase 2: per-role register gather (stride 27: conflict-free) ----
    float b[27], a[15];   // a[j] = t1[role*12 + j]
    #pragma unroll
    for (int j = 0; j < 27; j++) b[j] = s[PPB * 27 + p * 27 + j];
    {
        const int abase = p * 27 + role * 12;
        #pragma unroll
        for (int j = 0; j < 15; j++) a[j] = s[abase + j];
    }
    __syncthreads();   // B2: inputs consumed; s reusable for out1 staging

    const float n1 = 0.5773502691896258f;   // 1/sqrt(3)
    const float n2 = 0.3333333333333333f;   // 1/3
    const float n3 = 0.1924500897298753f;   // 1/sqrt(27)

    float d;   // out3 partial (both roles)

    if (role == 0) {
        // out1 rows xy = 0..3 -> s
        #pragma unroll
        for (int xy = 0; xy < 4; xy++) {
            const float c0 = a[xy * 3 + 0] * n1;
            const float c1 = a[xy * 3 + 1] * n1;
            const float c2 = a[xy * 3 + 2] * n1;
            #pragma unroll
            for (int uv = 0; uv < 9; uv++)
                s[p * 81 + xy * 9 + uv] = c0 * b[uv] + c1 * b[9 + uv] + c2 * b[18 + uv];
        }
        // out2 x=0 full -> st2 slots 0..2
        #pragma unroll
        for (int u = 0; u < 3; u++) {
            float r = 0.0f;
            #pragma unroll
            for (int kl = 0; kl < 9; kl++) r += a[kl] * b[kl * 3 + u];
            st2[p * 9 + u] = r * n2;
        }
        // out2 x=1 partial, kl=0..2 (t1[9..11]) -> aux
        #pragma unroll
        for (int u = 0; u < 3; u++)
            aux[p * 4 + u] = a[9] * b[u] + a[10] * b[3 + u] + a[11] * b[6 + u];
        // out3 partial j=0..11 -> aux
        d = 0.0f;
        #pragma unroll
        for (int j = 0; j < 12; j++) d += a[j] * b[j];
        aux[p * 4 + 3] = d;
    } else {
        // a[j] = t1[12+j]
        // out1 rows xy = 4..8 -> s
        #pragma unroll
        for (int xy = 4; xy < 9; xy++) {
            const float c0 = a[xy * 3 - 12] * n1;
            const float c1 = a[xy * 3 - 11] * n1;
            const float c2 = a[xy * 3 - 10] * n1;
            #pragma unroll
            for (int uv = 0; uv < 9; uv++)
                s[p * 81 + xy * 9 + uv] = c0 * b[uv] + c1 * b[9 + uv] + c2 * b[18 + uv];
        }
        // out2 x=2 full: t1[18+kl] = a[6+kl] -> st2 slots 6..8
        #pragma unroll
        for (int u = 0; u < 3; u++) {
            float r = 0.0f;
            #pragma unroll
            for (int kl = 0; kl < 9; kl++) r += a[6 + kl] * b[kl * 3 + u];
            st2[p * 9 + 6 + u] = r * n2;
        }
        // out3 partial j=12..26
        d = 0.0f;
        #pragma unroll
        for (int j = 0; j < 15; j++) d += a[j] * b[12 + j];
    }
    __syncthreads();   // B3: out1 fully staged; role-0 partials published

    // ---- Kick out1 bulk store immediately (async engine, 20736 B) ----
    if (tid == 0) {
        asm volatile("fence.proxy.async.shared::cta;" ::: "memory");
        asm volatile("cp.async.bulk.global.shared::cta.bulk_group [%0], [%1], %2;"
                     :: "l"(out + p0 * 81), "r"(smem_u32(s)),
                        "r"((uint32_t)(PPB * 81 * 4)) : "memory");
        asm volatile("cp.async.bulk.commit_group;" ::: "memory");
    }

    if (role == 1) {
        // out2 x=1: combine partials -> st2 slots 3..5
        #pragma unroll
        for (int u = 0; u < 3; u++) {
            float r = aux[p * 4 + u];
            #pragma unroll
            for (int kl = 3; kl < 9; kl++) r += a[kl - 3] * b[kl * 3 + u];
            st2[p * 9 + 3 + u] = r * n2;
        }
        // out3: combine + coalesced streaming store
        __stcs(out + (long long)npairs * 90 + p0 + p, (d + aux[p * 4 + 3]) * n3);
    }
    __syncthreads();   // B4: st2 fully written

    // ---- out2 bulk store (2304 B), then drain both groups ----
    if (tid == 0) {
        asm volatile("fence.proxy.async.shared::cta;" ::: "memory");
        asm volatile("cp.async.bulk.global.shared::cta.bulk_group [%0], [%1], %2;"
                     :: "l"(out + (long long)npairs * 81 + p0 * 9),
                        "r"(smem_u32(st2)),
                        "r"((uint32_t)(PPB * 9 * 4)) : "memory");
        asm volatile("cp.async.bulk.commit_group;" ::: "memory");
        // smem must stay live until the engine has READ it.
        asm volatile("cp.async.bulk.wait_group.read 0;" ::: "memory");
    }
}

extern "C" void kernel_launch(void* const* d_in, const int* in_sizes, int n_in,
                              void* d_out, int out_size)
{
    const float* T1 = (const float*)d_in[0];
    const float* T2 = (const float*)d_in[1];
    float* out = (float*)d_out;

    const int npairs = in_sizes[0] / 27;     // 1,048,576
    const int grid = npairs / PPB;           // 16384

    broadcast_tc_kernel<<<grid, THREADS>>>(T1, T2, out, npairs);
}

// round 13
// speedup vs baseline: 1.1551x; 1.0014x over previous
#include <cuda_runtime.h>
#include <cstdint>

// BroadcastTC on GB300, round 13: R12 pipeline (cp.async in, cp.async.bulk out)
// scaled to 128 pairs / 256 threads per block. npairs = B*C = 1,048,576.
//   out1[xy,uv] = sum_k t1[xy*3+k]*t2[k*9+uv] / sqrt(3)   (81 floats)
//   out2[x,u]   = sum_kl t1[x*9+kl]*t2[kl*3+u] / 3        (9 floats)
//   out3        = dot(t1,t2) / sqrt(27)                   (1 float)
// Output layout: [out1 flat | out2 flat | out3 flat].
//
// Role split (warp-uniform): threads p (role 0) and p+128 (role 1) share pair p.

#define PPB 128
#define THREADS 256

__device__ __forceinline__ uint32_t smem_u32(const void* p) {
    uint32_t a;
    asm("{ .reg .u64 t; cvta.to.shared.u64 t, %1; cvt.u32.u64 %0, t; }"
        : "=r"(a) : "l"(p));
    return a;
}

__global__ __launch_bounds__(THREADS, 4)
void broadcast_tc_kernel(const float* __restrict__ T1,
                         const float* __restrict__ T2,
                         float* __restrict__ out,
                         int npairs)
{
    // s: inputs (t1 at [0..3455], t2 at [3456..6911]) then out1 staging.
    __shared__ __align__(16) float s[PPB * 81];    // 41472 B
    __shared__ __align__(16) float st2[PPB * 9];   // 4608 B (out2 staging)
    __shared__ float aux[PPB * 4];                 // 2048 B (role-0 partials)
                                                   // total 48128 B < 48 KB

    const int tid  = threadIdx.x;
    const int p    = tid & (PPB - 1);
    const int role = tid >> 7;                     // warp-uniform
    const long long p0 = (long long)blockIdx.x * PPB;

    // ---- Phase 1: cp.async input staging (1728 float4, L1-bypass) ----
    {
        const float4* g1 = (const float4*)(T1 + p0 * 27);   // 864 float4
        const float4* g2 = (const float4*)(T2 + p0 * 27);   // 864 float4
        const uint32_t sb = smem_u32(s);
        #pragma unroll
        for (int t = 0; t < 7; t++) {
            const int i = tid + t * THREADS;
            if (i < 1728) {
                const float4* src = (i < 864) ? (g1 + i) : (g2 + (i - 864));
                asm volatile("cp.async.cg.shared.global [%0], [%1], 16;"
                             :: "r"(sb + i * 16), "l"(src) : "memory");
            }
        }
        asm volatile("cp.async.commit_group;" ::: "memory");
        asm volatile("cp.async.wait_group 0;" ::: "memory");
    }
    __syncthreads();   // B1: inputs visible

    // ---- Phase 2: per-role register gather (stride 27: conflict-free) ----
    float b[27], a[15];   // a[j] = t1[role*12 + j]
    #pragma unroll
    for (int j = 0; j < 27; j++) b[j] = s[PPB * 27 + p * 27 + j];
    {
        const int abase = p * 27 + role * 12;
        #pragma unroll
        for (int j = 0; j < 15; j++) a[j] = s[abase + j];
    }
    __syncthreads();   // B2: inputs consumed; s reusable for out1 staging

    const float n1 = 0.5773502691896258f;   // 1/sqrt(3)
    const float n2 = 0.3333333333333333f;   // 1/3
    const float n3 = 0.1924500897298753f;   // 1/sqrt(27)

    float d;   // out3 partial (both roles)

    if (role == 0) {
        // out1 rows xy = 0..3 -> s
        #pragma unroll
        for (int xy = 0; xy < 4; xy++) {
            const float c0 = a[xy * 3 + 0] * n1;
            const float c1 = a[xy * 3 + 1] * n1;
            const float c2 = a[xy * 3 + 2] * n1;
            #pragma unroll
            for (int uv = 0; uv < 9; uv++)
                s[p * 81 + xy * 9 + uv] = c0 * b[uv] + c1 * b[9 + uv] + c2 * b[18 + uv];
        }
        // out2 x=0 full -> st2 slots 0..2
        #pragma unroll
        for (int u = 0; u < 3; u++) {
            float r = 0.0f;
            #pragma unroll
            for (int kl = 0; kl < 9; kl++) r += a[kl] * b[kl * 3 + u];
            st2[p * 9 + u] = r * n2;
        }
        // out2 x=1 partial, kl=0..2 (t1[9..11]) -> aux
        #pragma unroll
        for (int u = 0; u < 3; u++)
            aux[p * 4 + u] = a[9] * b[u] + a[10] * b[3 + u] + a[11] * b[6 + u];
        // out3 partial j=0..11 -> aux
        d = 0.0f;
        #pragma unroll
        for (int j = 0; j < 12; j++) d += a[j] * b[j];
        aux[p * 4 + 3] = d;
    } else {
        // a[j] = t1[12+j]
        // out1 rows xy = 4..8 -> s
        #pragma unroll
        for (int xy = 4; xy < 9; xy++) {
            const float c0 = a[xy * 3 - 12] * n1;
            const float c1 = a[xy * 3 - 11] * n1;
            const float c2 = a[xy * 3 - 10] * n1;
            #pragma unroll
            for (int uv = 0; uv < 9; uv++)
                s[p * 81 + xy * 9 + uv] = c0 * b[uv] + c1 * b[9 + uv] + c2 * b[18 + uv];
        }
        // out2 x=2 full: t1[18+kl] = a[6+kl] -> st2 slots 6..8
        #pragma unroll
        for (int u = 0; u < 3; u++) {
            float r = 0.0f;
            #pragma unroll
            for (int kl = 0; kl < 9; kl++) r += a[6 + kl] * b[kl * 3 + u];
            st2[p * 9 + 6 + u] = r * n2;
        }
        // out3 partial j=12..26
        d = 0.0f;
        #pragma unroll
        for (int j = 0; j < 15; j++) d += a[j] * b[12 + j];
    }
    __syncthreads();   // B3: out1 fully staged; role-0 partials published

    // ---- Kick out1 bulk store immediately (async engine, 41472 B) ----
    if (tid == 0) {
        asm volatile("fence.proxy.async.shared::cta;" ::: "memory");
        asm volatile("cp.async.bulk.global.shared::cta.bulk_group [%0], [%1], %2;"
                     :: "l"(out + p0 * 81), "r"(smem_u32(s)),
                        "r"((uint32_t)(PPB * 81 * 4)) : "memory");
        asm volatile("cp.async.bulk.commit_group;" ::: "memory");
    }

    if (role == 1) {
        // out2 x=1: combine partials -> st2 slots 3..5
        #pragma unroll
        for (int u = 0; u < 3; u++) {
            float r = aux[p * 4 + u];
            #pragma unroll
            for (int kl = 3; kl < 9; kl++) r += a[kl - 3] * b[kl * 3 + u];
            st2[p * 9 + 3 + u] = r * n2;
        }
        // out3: combine + coalesced streaming store (128 contiguous floats)
        __stcs(out + (long long)npairs * 90 + p0 + p, (d + aux[p * 4 + 3]) * n3);
    }
    __syncthreads();   // B4: st2 fully written

    // ---- out2 bulk store (4608 B), then drain both groups ----
    if (tid == 0) {
        asm volatile("fence.proxy.async.shared::cta;" ::: "memory");
        asm volatile("cp.async.bulk.global.shared::cta.bulk_group [%0], [%1], %2;"
                     :: "l"(out + (long long)npairs * 81 + p0 * 9),
                        "r"(smem_u32(st2)),
                        "r"((uint32_t)(PPB * 9 * 4)) : "memory");
        asm volatile("cp.async.bulk.commit_group;" ::: "memory");
        // smem must stay live until the engine has READ it.
        asm volatile("cp.async.bulk.wait_group.read 0;" ::: "memory");
    }
}

extern "C" void kernel_launch(void* const* d_in, const int* in_sizes, int n_in,
                              void* d_out, int out_size)
{
    const float* T1 = (const float*)d_in[0];
    const float* T2 = (const float*)d_in[1];
    float* out = (float*)d_out;

    const int npairs = in_sizes[0] / 27;     // 1,048,576
    const int grid = npairs / PPB;           // 8192

    broadcast_tc_kernel<<<grid, THREADS>>>(T1, T2, out, npairs);
}